// round 2
// baseline (speedup 1.0000x reference)
#include <cuda_runtime.h>
#include <cstdint>

#define E_ 8
#define D_ 512
#define P_ 32
#define TOK_PER_WARP 4
#define WARPS_ 8
#define TOK_PER_BLOCK (TOK_PER_WARP * WARPS_)
#define DC 16            // d-chunk cached in registers
#define FULLM 0xffffffffu

// scratch (no cudaMalloc allowed)
__device__ float g_protoT[E_ * D_ * P_];   // [e][d][p]
__device__ float g_p2[E_ * P_];
__device__ int   g_zero = 0;

// ---------------- prep kernels ----------------
__global__ void prep_transpose(const float* __restrict__ proto) {
    int o = blockIdx.x * blockDim.x + threadIdx.x;      // over E*D*P
    if (o >= E_ * D_ * P_) return;
    int p = o & (P_ - 1);
    int d = (o >> 5) & (D_ - 1);
    int e = o >> 14;
    g_protoT[o] = proto[(e * P_ + p) * D_ + d];
}

__global__ void prep_p2(const float* __restrict__ proto) {
    int ep = blockIdx.x;                 // one warp-block per (e,p)
    int lane = threadIdx.x;
    const float* row = proto + (size_t)ep * D_;
    float s = 0.f;
    for (int d = lane; d < D_; d += 32) { float v = row[d]; s = fmaf(v, v, s); }
    #pragma unroll
    for (int o = 16; o; o >>= 1) s += __shfl_xor_sync(FULLM, s, o);
    if (lane == 0) g_p2[ep] = s;
}

// ---------------- main kernel ----------------
__global__ __launch_bounds__(256, 3)
void ot_noise_gate_kernel(const float* __restrict__ tokens,
                          const int* __restrict__ fi_ptr,
                          float* __restrict__ out, int B) {
    extern __shared__ float smem[];
    float*  protoT_s = smem;                         // D_*P_ floats = 64KB
    float*  p2_s     = smem + D_ * P_;               // P_ floats
    float4* chunkbuf = (float4*)(p2_s + P_);         // WARPS_ * 8 vec * 4 float4

    const int e    = blockIdx.y;
    const int fi   = *fi_ptr;
    const int tid  = threadIdx.x;
    const int warp = tid >> 5;
    const int lane = tid & 31;
    const int BE   = B * E_;
    const int b0   = blockIdx.x * TOK_PER_BLOCK;

    if (e == fi) {
        // trivial outputs for the full/anchor expert
        if (tid < TOK_PER_BLOCK) {
            int b = b0 + tid;
            out[b * E_ + e]      = 1.0f;
            out[BE + b * E_ + e] = 0.0f;
        }
        return;
    }

    // stage prototypes (transposed) + p2 for this expert
    {
        const float4* gp = (const float4*)(g_protoT + (size_t)e * D_ * P_);
        float4* ps = (float4*)protoT_s;
        #pragma unroll
        for (int i = tid; i < D_ * P_ / 4; i += 256) ps[i] = gp[i];
        if (tid < P_) p2_s[tid] = g_p2[e * P_ + tid];
    }
    __syncthreads();

    // this warp handles 4 consecutive tokens
    const int bw   = b0 + warp * TOK_PER_WARP;
    const int vec  = lane >> 2;          // 0..3 tokens, 4..7 anchors
    const int part = lane & 3;
    const int tvec = (vec < 4) ? vec : vec - 4;
    const int col  = (vec < 4) ? e : fi;
    const float4* gsrc =
        (const float4*)(tokens + ((size_t)(bw + tvec) * E_ + col) * D_);
    float4* mybuf = chunkbuf + warp * 32;  // 8 vec * 4 parts

    float ct[4] = {0.f, 0.f, 0.f, 0.f};
    float ca[4] = {0.f, 0.f, 0.f, 0.f};
    float nrm = 0.f;

    #pragma unroll 1
    for (int c = 0; c < D_ / DC; ++c) {
        const int d0 = c * DC;
        // stage 16 d's of 4 tokens + 4 anchors (each lane: one float4)
        float4 v = gsrc[(d0 >> 2) + part];
        nrm = fmaf(v.x, v.x, fmaf(v.y, v.y, fmaf(v.z, v.z, fmaf(v.w, v.w, nrm))));
        __syncwarp();
        mybuf[vec * 4 + part] = v;
        __syncwarp();

        // register-cache proto chunk: lane = prototype index
        float pr[DC];
        #pragma unroll
        for (int i = 0; i < DC; ++i)
            pr[i] = protoT_s[(d0 + i) * P_ + lane];

        #pragma unroll
        for (int t = 0; t < 4; ++t) {
            #pragma unroll
            for (int q = 0; q < 4; ++q) {
                float4 tv = mybuf[t * 4 + q];        // broadcast
                float4 av = mybuf[(t + 4) * 4 + q];  // broadcast
                ct[t] = fmaf(pr[q * 4 + 0], tv.x, ct[t]);
                ct[t] = fmaf(pr[q * 4 + 1], tv.y, ct[t]);
                ct[t] = fmaf(pr[q * 4 + 2], tv.z, ct[t]);
                ct[t] = fmaf(pr[q * 4 + 3], tv.w, ct[t]);
                ca[t] = fmaf(pr[q * 4 + 0], av.x, ca[t]);
                ca[t] = fmaf(pr[q * 4 + 1], av.y, ca[t]);
                ca[t] = fmaf(pr[q * 4 + 2], av.z, ca[t]);
                ca[t] = fmaf(pr[q * 4 + 3], av.w, ca[t]);
            }
        }
    }

    // norms: reduce over the 4 parts of each vec group, then broadcast
    nrm += __shfl_xor_sync(FULLM, nrm, 1);
    nrm += __shfl_xor_sync(FULLM, nrm, 2);
    float t2[4], a2[4];
    #pragma unroll
    for (int t = 0; t < 4; ++t) {
        t2[t] = __shfl_sync(FULLM, nrm, t * 4);
        a2[t] = __shfl_sync(FULLM, nrm, 16 + t * 4);
    }

    // cost rows and kernel K = exp(-cost/eps), eps = 0.05
    const float p2v = p2_s[lane];
    float c0[4], c1[4], ka[4], kb[4], Sa[4], Sb[4], r[4];
    #pragma unroll
    for (int t = 0; t < 4; ++t) {
        c0[t] = fmaxf(fmaf(-2.f, ct[t], t2[t]) + p2v, 0.f);
        c1[t] = fmaxf(fmaf(-2.f, ca[t], a2[t]) + p2v, 0.f);
        ka[t] = __expf(c0[t] * -20.f);
        kb[t] = __expf(c1[t] * -20.f);
        Sa[t] = ka[t];
        Sb[t] = kb[t];
    }
    #pragma unroll
    for (int o = 16; o; o >>= 1) {
        #pragma unroll
        for (int t = 0; t < 4; ++t) {
            Sa[t] += __shfl_xor_sync(FULLM, Sa[t], o);
            Sb[t] += __shfl_xor_sync(FULLM, Sb[t], o);
        }
    }
    #pragma unroll
    for (int t = 0; t < 4; ++t) r[t] = __fdividef(Sa[t], Sb[t]);

    // 49 remaining Sinkhorn iterations, collapsed to scalar ratio t = u1/u0
    #pragma unroll 1
    for (int it = 0; it < 49; ++it) {
        float S[4];
        #pragma unroll
        for (int t = 0; t < 4; ++t) {
            float m = fmaf(kb[t], r[t], ka[t]);
            S[t] = __fdividef(ka[t], m);
        }
        #pragma unroll
        for (int o = 16; o; o >>= 1) {
            #pragma unroll
            for (int t = 0; t < 4; ++t)
                S[t] += __shfl_xor_sync(FULLM, S[t], o);
        }
        #pragma unroll
        for (int t = 0; t < 4; ++t)
            r[t] = __fdividef(S[t] * r[t], 32.f - S[t]);
    }

    // transport: T[0,p] = nu*w, T[1,p] = nu*(1-w), w = a/(a+b*t50)
    float ot[4];
    #pragma unroll
    for (int t = 0; t < 4; ++t) {
        float m = fmaf(kb[t], r[t], ka[t]);
        float w = __fdividef(ka[t], m);
        ot[t] = fmaf(w, c0[t] - c1[t], c1[t]);   // w*c0 + (1-w)*c1
    }
    #pragma unroll
    for (int o = 16; o; o >>= 1) {
        #pragma unroll
        for (int t = 0; t < 4; ++t)
            ot[t] += __shfl_xor_sync(FULLM, ot[t], o);
    }

    if (lane < 4) {
        int t = lane;
        int b = bw + t;
        float o_ = ot[t] * (1.f / 32.f);
        float val = __fdividef(1.f, 1.f + __expf(6.f * (o_ - 0.25f)));
        out[b * E_ + e]      = val;
        out[BE + b * E_ + e] = o_;
    }
}

// ---------------- launch ----------------
extern "C" void kernel_launch(void* const* d_in, const int* in_sizes, int n_in,
                              void* d_out, int out_size) {
    const float* tokens = (const float*)d_in[0];
    const float* proto  = (const float*)d_in[1];
    const int* fi;
    if (n_in >= 3) {
        fi = (const int*)d_in[2];
    } else {
        void* zp = nullptr;
        cudaGetSymbolAddress(&zp, g_zero);
        fi = (const int*)zp;
    }
    float* out = (float*)d_out;
    const int B = in_sizes[0] / (E_ * D_);

    prep_transpose<<<(E_ * D_ * P_ + 255) / 256, 256>>>(proto);
    prep_p2<<<E_ * P_, 32>>>(proto);

    const size_t smem = (size_t)(D_ * P_ + P_) * sizeof(float)
                      + (size_t)WARPS_ * 32 * sizeof(float4);  // 69760 B
    cudaFuncSetAttribute(ot_noise_gate_kernel,
                         cudaFuncAttributeMaxDynamicSharedMemorySize, (int)smem);

    dim3 grid(B / TOK_PER_BLOCK, E_);
    ot_noise_gate_kernel<<<grid, 256, smem>>>(tokens, fi, out, B);
}

// round 5
// speedup vs baseline: 1.2853x; 1.2853x over previous
#include <cuda_runtime.h>
#include <cuda_bf16.h>
#include <cstdint>

#define E_ 8
#define D_ 512
#define P_ 32
#define MTOK 64             // tokens per CTA; M = 128 rows (64 token + 64 anchor)
#define THREADS 256
#define FULLM 0xffffffffu

// padded bf16 row: 512 + 8 = 520 elems = 1040 bytes (16B shift per row -> ldsm conflict-free)
#define ROWB 1040

// ---- smem layout (bytes) ----
#define SM_A     0                         // 128 * 1040 = 133120
#define SM_B     133120                    // 32 * 1040  = 33280  -> 166400
#define SM_S2    166400                    // 128 floats -> 166912
#define SM_P2    166912                    // 32 floats  -> 167040
#define SMEM_BYTES 167040
#define SM_CROSS 0                         // reuse A region: cross[128][34] floats (17408 B)

__device__ int g_zero = 0;

static __device__ __forceinline__ uint32_t smem_u32(const void* p) {
    return (uint32_t)__cvta_generic_to_shared(p);
}

#define LDSM_X4(r0, r1, r2, r3, addr) \
    asm volatile("ldmatrix.sync.aligned.m8n8.x4.shared.b16 {%0,%1,%2,%3}, [%4];" \
        : "=r"(r0), "=r"(r1), "=r"(r2), "=r"(r3) : "r"(addr))

static __device__ __forceinline__ void mma16816(float* d, const uint32_t* a,
                                                uint32_t b0, uint32_t b1) {
    asm volatile(
        "mma.sync.aligned.m16n8k16.row.col.f32.bf16.bf16.f32 "
        "{%0,%1,%2,%3}, {%4,%5,%6,%7}, {%8,%9}, {%0,%1,%2,%3};"
        : "+f"(d[0]), "+f"(d[1]), "+f"(d[2]), "+f"(d[3])
        : "r"(a[0]), "r"(a[1]), "r"(a[2]), "r"(a[3]), "r"(b0), "r"(b1));
}

__global__ __launch_bounds__(THREADS)
void otng_hmma(const float* __restrict__ tokens,
               const float* __restrict__ protos,
               const int* __restrict__ fi_ptr,
               float* __restrict__ out, int B) {
    extern __shared__ char smem[];
    const int e    = blockIdx.x;
    const int fi   = *fi_ptr;
    const int b0   = blockIdx.y * MTOK;
    const int tid  = threadIdx.x;
    const int wid  = tid >> 5;
    const int lane = tid & 31;
    const int BE   = B * E_;

    if (e == fi) {                        // trivial expert
        if (tid < MTOK) {
            int b = b0 + tid;
            out[b * E_ + e]      = 1.0f;
            out[BE + b * E_ + e] = 0.0f;
        }
        return;
    }

    const uint32_t sbase = smem_u32(smem);
    float* s2s = (float*)(smem + SM_S2);
    float* p2s = (float*)(smem + SM_P2);

    // ---- stage A: rows 0-63 tokens[b][e], rows 64-127 tokens[b][fi] (bf16 + norms) ----
    #pragma unroll 1
    for (int k = 0; k < 16; ++k) {
        const int row = wid + k * 8;                  // 0..127
        const int bt  = b0 + (row & 63);
        const int col = (row < 64) ? e : fi;
        const float4* src = (const float4*)(tokens + ((size_t)bt * E_ + col) * D_);
        float nrm = 0.f;
        #pragma unroll
        for (int j = 0; j < 4; ++j) {
            float4 v = src[j * 32 + lane];            // d = j*128 + lane*4
            __nv_bfloat162 h0 = __floats2bfloat162_rn(v.x, v.y);
            __nv_bfloat162 h1 = __floats2bfloat162_rn(v.z, v.w);
            float2 f0 = __bfloat1622float2(h0);
            float2 f1 = __bfloat1622float2(h1);
            nrm = fmaf(f0.x, f0.x, fmaf(f0.y, f0.y,
                  fmaf(f1.x, f1.x, fmaf(f1.y, f1.y, nrm))));
            uint2 pk;
            pk.x = *reinterpret_cast<uint32_t*>(&h0);
            pk.y = *reinterpret_cast<uint32_t*>(&h1);
            *reinterpret_cast<uint2*>(smem + SM_A + row * ROWB + j * 256 + lane * 8) = pk;
        }
        #pragma unroll
        for (int o = 16; o; o >>= 1) nrm += __shfl_xor_sync(FULLM, nrm, o);
        if (lane == 0) s2s[row] = nrm;
    }

    // ---- stage B: 32 prototypes of expert e ----
    #pragma unroll 1
    for (int k = 0; k < 4; ++k) {
        const int p = wid + k * 8;                    // 0..31
        const float4* src = (const float4*)(protos + ((size_t)e * P_ + p) * D_);
        float nrm = 0.f;
        #pragma unroll
        for (int j = 0; j < 4; ++j) {
            float4 v = src[j * 32 + lane];
            __nv_bfloat162 h0 = __floats2bfloat162_rn(v.x, v.y);
            __nv_bfloat162 h1 = __floats2bfloat162_rn(v.z, v.w);
            float2 f0 = __bfloat1622float2(h0);
            float2 f1 = __bfloat1622float2(h1);
            nrm = fmaf(f0.x, f0.x, fmaf(f0.y, f0.y,
                  fmaf(f1.x, f1.x, fmaf(f1.y, f1.y, nrm))));
            uint2 pk;
            pk.x = *reinterpret_cast<uint32_t*>(&h0);
            pk.y = *reinterpret_cast<uint32_t*>(&h1);
            *reinterpret_cast<uint2*>(smem + SM_B + p * ROWB + j * 256 + lane * 8) = pk;
        }
        #pragma unroll
        for (int o = 16; o; o >>= 1) nrm += __shfl_xor_sync(FULLM, nrm, o);
        if (lane == 0) p2s[p] = nrm;
    }
    __syncthreads();

    // ---- HMMA GEMM: each warp does M=16 rows x N=32 x K=512 ----
    float acc[16];
    #pragma unroll
    for (int i = 0; i < 16; ++i) acc[i] = 0.f;
    {
        const int row0 = wid * 16;
        uint32_t aAddr = sbase + SM_A + (uint32_t)(row0 + (lane & 15)) * ROWB
                       + (uint32_t)((lane >> 4) * 16);           // +8 bf16 cols = 16 B
        const int bn  = (lane & 7) + ((lane >> 4) << 3);
        const int bk  = ((lane >> 3) & 1) * 8;
        uint32_t bAddr0 = sbase + SM_B + (uint32_t)bn * ROWB + (uint32_t)(bk * 2);
        uint32_t bAddr1 = bAddr0 + 16u * ROWB;

        #pragma unroll 4
        for (int s = 0; s < 32; ++s) {
            uint32_t a[4], p0, p1, p2, p3, q0, q1, q2, q3;
            LDSM_X4(a[0], a[1], a[2], a[3], aAddr + s * 32);
            LDSM_X4(p0, p1, p2, p3, bAddr0 + s * 32);
            LDSM_X4(q0, q1, q2, q3, bAddr1 + s * 32);
            mma16816(acc + 0,  a, p0, p1);   // n 0-7
            mma16816(acc + 4,  a, p2, p3);   // n 8-15
            mma16816(acc + 8,  a, q0, q1);   // n 16-23
            mma16816(acc + 12, a, q2, q3);   // n 24-31
        }
    }
    __syncthreads();   // all ldmatrix reads of A done -> safe to overwrite with cross

    // ---- scatter accumulators to cross[128][34] ----
    float* crossS = (float*)(smem + SM_CROSS);
    {
        const int r0 = wid * 16 + (lane >> 2);
        const int c0 = 2 * (lane & 3);
        #pragma unroll
        for (int nt = 0; nt < 4; ++nt) {
            const int col = nt * 8 + c0;
            *(float2*)(crossS + (size_t)r0 * 34 + col)       = make_float2(acc[nt*4+0], acc[nt*4+1]);
            *(float2*)(crossS + (size_t)(r0 + 8) * 34 + col) = make_float2(acc[nt*4+2], acc[nt*4+3]);
        }
    }
    __syncthreads();

    // ---- epilogue: Sinkhorn collapsed to scalar root-find  S(r)=sum_p 1/(1+c_p r)=16 ----
    const float p2v = p2s[lane];
    float cp[8], r[8], d01[8], c1v[8], Sa[8], Sb[8];
    #pragma unroll
    for (int t = 0; t < 8; ++t) {
        const int m = wid * 8 + t;
        float ct = crossS[(size_t)m * 34 + lane];
        float ca = crossS[(size_t)(64 + m) * 34 + lane];
        float c0 = fmaxf(fmaf(-2.f, ct, s2s[m])      + p2v, 0.f);
        float c1 = fmaxf(fmaf(-2.f, ca, s2s[64 + m]) + p2v, 0.f);
        d01[t] = c0 - c1;
        c1v[t] = c1;
        cp[t]  = __expf(20.f * (c0 - c1));            // kb/ka
        Sa[t]  = __expf(-20.f * c0);
        Sb[t]  = __expf(-20.f * c1);
    }
    #pragma unroll
    for (int o = 16; o; o >>= 1) {
        #pragma unroll
        for (int t = 0; t < 8; ++t) {
            Sa[t] += __shfl_xor_sync(FULLM, Sa[t], o);
            Sb[t] += __shfl_xor_sync(FULLM, Sb[t], o);
        }
    }
    #pragma unroll
    for (int t = 0; t < 8; ++t) r[t] = __fdividef(Sa[t], Sb[t]);   // reference iter 1

    #pragma unroll 1
    for (int it = 0; it < 12; ++it) {                  // Newton (monotone, convex)
        float f[8], g[8];
        #pragma unroll
        for (int t = 0; t < 8; ++t) {
            float u = __frcp_rn(fmaf(cp[t], r[t], 1.f));
            f[t] = u;
            g[t] = cp[t] * u * u;
        }
        #pragma unroll
        for (int o = 16; o; o >>= 1) {
            #pragma unroll
            for (int t = 0; t < 8; ++t) {
                f[t] += __shfl_xor_sync(FULLM, f[t], o);
                g[t] += __shfl_xor_sync(FULLM, g[t], o);
            }
        }
        #pragma unroll
        for (int t = 0; t < 8; ++t) {
            float rn = fmaf(f[t] - 16.f, __frcp_rn(g[t]), r[t]);
            r[t] = (rn > 0.f) ? rn : r[t] * 0.5f;
        }
    }

    float ot[8];
    #pragma unroll
    for (int t = 0; t < 8; ++t) {
        float w = __frcp_rn(fmaf(cp[t], r[t], 1.f));
        ot[t] = fmaf(w, d01[t], c1v[t]);               // w*c0 + (1-w)*c1
    }
    #pragma unroll
    for (int o = 16; o; o >>= 1) {
        #pragma unroll
        for (int t = 0; t < 8; ++t) ot[t] += __shfl_xor_sync(FULLM, ot[t], o);
    }
    if (lane == 0) {
        #pragma unroll
        for (int t = 0; t < 8; ++t) {
            const int b = b0 + wid * 8 + t;
            float o_  = ot[t] * (1.f / 32.f);
            float val = __fdividef(1.f, 1.f + __expf(6.f * (o_ - 0.25f)));
            out[b * E_ + e]      = val;
            out[BE + b * E_ + e] = o_;
        }
    }
}

// ---------------- launch ----------------
extern "C" void kernel_launch(void* const* d_in, const int* in_sizes, int n_in,
                              void* d_out, int out_size) {
    const float* tokens = (const float*)d_in[0];
    const float* protos = (const float*)d_in[1];
    const int* fi;
    if (n_in >= 3) {
        fi = (const int*)d_in[2];
    } else {
        void* zp = nullptr;
        cudaGetSymbolAddress(&zp, g_zero);
        fi = (const int*)zp;
    }
    float* out = (float*)d_out;
    const int B = in_sizes[0] / (E_ * D_);

    cudaFuncSetAttribute(otng_hmma,
                         cudaFuncAttributeMaxDynamicSharedMemorySize, SMEM_BYTES);
    dim3 grid(E_, B / MTOK);
    otng_hmma<<<grid, THREADS, SMEM_BYTES>>>(tokens, protos, fi, out, B);
}

// round 6
// speedup vs baseline: 2.0020x; 1.5576x over previous
#include <cuda_runtime.h>
#include <cuda_bf16.h>
#include <cstdint>

#define E_ 8
#define D_ 512
#define P_ 32
#define MTOK 64             // tokens per CTA; M = 128 rows (64 token + 64 anchor)
#define THREADS 256
#define FULLM 0xffffffffu

// padded bf16 row for B tile: 512 + 8 = 520 elems = 1040 B (ldmatrix conflict-free)
#define ROWB 1040

// ---- smem layout (bytes) ----
#define SM_B     0                       // 32 * 1040 = 33280; reused as cross[128][34] after MMA
#define SM_S2    33280                   // 128 floats
#define SM_P2    33792                   // 32 floats
#define SMEM_BYTES 33920
#define SM_CROSS 0

__device__ int g_zero = 0;

static __device__ __forceinline__ uint32_t smem_u32(const void* p) {
    return (uint32_t)__cvta_generic_to_shared(p);
}

#define LDSM_X4(r0, r1, r2, r3, addr) \
    asm volatile("ldmatrix.sync.aligned.m8n8.x4.shared.b16 {%0,%1,%2,%3}, [%4];" \
        : "=r"(r0), "=r"(r1), "=r"(r2), "=r"(r3) : "r"(addr))

static __device__ __forceinline__ void mma16816(float* d, const uint32_t* a,
                                                uint32_t b0, uint32_t b1) {
    asm volatile(
        "mma.sync.aligned.m16n8k16.row.col.f32.bf16.bf16.f32 "
        "{%0,%1,%2,%3}, {%4,%5,%6,%7}, {%8,%9}, {%0,%1,%2,%3};"
        : "+f"(d[0]), "+f"(d[1]), "+f"(d[2]), "+f"(d[3])
        : "r"(a[0]), "r"(a[1]), "r"(a[2]), "r"(a[3]), "r"(b0), "r"(b1));
}

static __device__ __forceinline__ uint32_t packbf(float2 v) {
    __nv_bfloat162 h = __floats2bfloat162_rn(v.x, v.y);
    return *reinterpret_cast<uint32_t*>(&h);
}

__global__ __launch_bounds__(THREADS, 4)
void otng_hmma(const float* __restrict__ tokens,
               const float* __restrict__ protos,
               const int* __restrict__ fi_ptr,
               float* __restrict__ out, int B) {
    extern __shared__ char smem[];
    const int e    = blockIdx.x;
    const int fi   = *fi_ptr;
    const int b0   = blockIdx.y * MTOK;
    const int tid  = threadIdx.x;
    const int wid  = tid >> 5;
    const int lane = tid & 31;
    const int BE   = B * E_;

    if (e == fi) {                        // trivial expert
        if (tid < MTOK) {
            int b = b0 + tid;
            out[b * E_ + e]      = 1.0f;
            out[BE + b * E_ + e] = 0.0f;
        }
        return;
    }

    const uint32_t sbase = smem_u32(smem);
    float* s2s = (float*)(smem + SM_S2);
    float* p2s = (float*)(smem + SM_P2);

    // ---- stage B: 32 prototypes of expert e (bf16 + fp32 norms) ----
    #pragma unroll 1
    for (int k = 0; k < 4; ++k) {
        const int p = wid + k * 8;                    // 0..31
        const float4* src = (const float4*)(protos + ((size_t)e * P_ + p) * D_);
        float nrm = 0.f;
        #pragma unroll
        for (int j = 0; j < 4; ++j) {
            float4 v = src[j * 32 + lane];
            nrm = fmaf(v.x, v.x, fmaf(v.y, v.y, fmaf(v.z, v.z, fmaf(v.w, v.w, nrm))));
            uint2 pk;
            pk.x = packbf(make_float2(v.x, v.y));
            pk.y = packbf(make_float2(v.z, v.w));
            *reinterpret_cast<uint2*>(smem + SM_B + p * ROWB + j * 256 + lane * 8) = pk;
        }
        #pragma unroll
        for (int o = 16; o; o >>= 1) nrm += __shfl_xor_sync(FULLM, nrm, o);
        if (lane == 0) p2s[p] = nrm;
    }
    __syncthreads();

    // ---- HMMA GEMM, A fragments loaded DIRECTLY from global ----
    // warp rows: r0 = wid*16 + (lane>>2), r1 = r0+8.  rows<64: tokens[b][e];
    // rows>=64: anchors tokens[b][fi].
    float acc[16];
    #pragma unroll
    for (int i = 0; i < 16; ++i) acc[i] = 0.f;
    float nrm0 = 0.f, nrm1 = 0.f;
    {
        const int gr  = lane >> 2;
        const int m   = lane & 3;
        const int r0  = wid * 16 + gr;                // r1 = r0 + 8, same region
        const int col = (r0 < 64) ? e : fi;
        const int bt0 = b0 + (r0 & 63);
        const float* pA0 = tokens + ((size_t)bt0 * E_ + col) * D_ + 2 * m;
        const float* pA1 = tokens + ((size_t)(bt0 + 8) * E_ + col) * D_ + 2 * m;

        const int bn  = (lane & 7) + ((lane >> 4) << 3);
        const int bk  = ((lane >> 3) & 1) * 8;
        const uint32_t bAddr0 = sbase + SM_B + (uint32_t)bn * ROWB + (uint32_t)(bk * 2);
        const uint32_t bAddr1 = bAddr0 + 16u * ROWB;

        #pragma unroll 2
        for (int s = 0; s < 32; ++s) {
            const int k0 = s * 16;
            float2 f0 = *(const float2*)(pA0 + k0);       // (r0,  k0+2m)
            float2 f1 = *(const float2*)(pA1 + k0);       // (r0+8,k0+2m)
            float2 f2 = *(const float2*)(pA0 + k0 + 8);   // (r0,  k0+8+2m)
            float2 f3 = *(const float2*)(pA1 + k0 + 8);   // (r0+8,k0+8+2m)
            uint32_t a[4];
            a[0] = packbf(f0); a[1] = packbf(f1); a[2] = packbf(f2); a[3] = packbf(f3);
            nrm0 = fmaf(f0.x, f0.x, fmaf(f0.y, f0.y, fmaf(f2.x, f2.x, fmaf(f2.y, f2.y, nrm0))));
            nrm1 = fmaf(f1.x, f1.x, fmaf(f1.y, f1.y, fmaf(f3.x, f3.x, fmaf(f3.y, f3.y, nrm1))));

            uint32_t p0, p1, p2, p3, q0, q1, q2, q3;
            LDSM_X4(p0, p1, p2, p3, bAddr0 + s * 32);
            LDSM_X4(q0, q1, q2, q3, bAddr1 + s * 32);
            mma16816(acc + 0,  a, p0, p1);   // n 0-7
            mma16816(acc + 4,  a, p2, p3);   // n 8-15
            mma16816(acc + 8,  a, q0, q1);   // n 16-23
            mma16816(acc + 12, a, q2, q3);   // n 24-31
        }

        // row norms (fp32 pre-rounding): reduce across the quad (k pieces)
        nrm0 += __shfl_xor_sync(FULLM, nrm0, 1);
        nrm0 += __shfl_xor_sync(FULLM, nrm0, 2);
        nrm1 += __shfl_xor_sync(FULLM, nrm1, 1);
        nrm1 += __shfl_xor_sync(FULLM, nrm1, 2);
        if (m == 0) { s2s[r0] = nrm0; s2s[r0 + 8] = nrm1; }
    }
    __syncthreads();   // all ldsm reads of B done -> safe to overwrite with cross

    // ---- scatter accumulators to cross[128][34] (reuses B region) ----
    float* crossS = (float*)(smem + SM_CROSS);
    {
        const int r0 = wid * 16 + (lane >> 2);
        const int c0 = 2 * (lane & 3);
        #pragma unroll
        for (int nt = 0; nt < 4; ++nt) {
            const int col = nt * 8 + c0;
            *(float2*)(crossS + (size_t)r0 * 34 + col)       = make_float2(acc[nt*4+0], acc[nt*4+1]);
            *(float2*)(crossS + (size_t)(r0 + 8) * 34 + col) = make_float2(acc[nt*4+2], acc[nt*4+3]);
        }
    }
    __syncthreads();

    // ---- epilogue: Sinkhorn collapsed to scalar root-find  S(r)=sum_p 1/(1+c_p r)=16 ----
    const float p2v = p2s[lane];
    float cp[8], r[8], d01[8], c1v[8], Sa[8], Sb[8];
    #pragma unroll
    for (int t = 0; t < 8; ++t) {
        const int m = wid * 8 + t;
        float ct = crossS[(size_t)m * 34 + lane];
        float ca = crossS[(size_t)(64 + m) * 34 + lane];
        float c0 = fmaxf(fmaf(-2.f, ct, s2s[m])      + p2v, 0.f);
        float c1 = fmaxf(fmaf(-2.f, ca, s2s[64 + m]) + p2v, 0.f);
        d01[t] = c0 - c1;
        c1v[t] = c1;
        cp[t]  = __expf(20.f * (c0 - c1));            // kb/ka
        Sa[t]  = __expf(-20.f * c0);
        Sb[t]  = __expf(-20.f * c1);
    }
    #pragma unroll
    for (int o = 16; o; o >>= 1) {
        #pragma unroll
        for (int t = 0; t < 8; ++t) {
            Sa[t] += __shfl_xor_sync(FULLM, Sa[t], o);
            Sb[t] += __shfl_xor_sync(FULLM, Sb[t], o);
        }
    }
    #pragma unroll
    for (int t = 0; t < 8; ++t) r[t] = __fdividef(Sa[t], Sb[t]);   // reference iter 1

    #pragma unroll 1
    for (int it = 0; it < 8; ++it) {                  // Newton (monotone, convex)
        float f[8], g[8];
        #pragma unroll
        for (int t = 0; t < 8; ++t) {
            float u = __frcp_rn(fmaf(cp[t], r[t], 1.f));
            f[t] = u;
            g[t] = cp[t] * u * u;
        }
        #pragma unroll
        for (int o = 16; o; o >>= 1) {
            #pragma unroll
            for (int t = 0; t < 8; ++t) {
                f[t] += __shfl_xor_sync(FULLM, f[t], o);
                g[t] += __shfl_xor_sync(FULLM, g[t], o);
            }
        }
        #pragma unroll
        for (int t = 0; t < 8; ++t) {
            float rn = fmaf(f[t] - 16.f, __frcp_rn(g[t]), r[t]);
            r[t] = (rn > 0.f) ? rn : r[t] * 0.5f;
        }
    }

    float ot[8];
    #pragma unroll
    for (int t = 0; t < 8; ++t) {
        float w = __frcp_rn(fmaf(cp[t], r[t], 1.f));
        ot[t] = fmaf(w, d01[t], c1v[t]);               // w*c0 + (1-w)*c1
    }
    #pragma unroll
    for (int o = 16; o; o >>= 1) {
        #pragma unroll
        for (int t = 0; t < 8; ++t) ot[t] += __shfl_xor_sync(FULLM, ot[t], o);
    }
    if (lane == 0) {
        #pragma unroll
        for (int t = 0; t < 8; ++t) {
            const int b = b0 + wid * 8 + t;
            float o_  = ot[t] * (1.f / 32.f);
            float val = __fdividef(1.f, 1.f + __expf(6.f * (o_ - 0.25f)));
            out[b * E_ + e]      = val;
            out[BE + b * E_ + e] = o_;
        }
    }
}

// ---------------- launch ----------------
extern "C" void kernel_launch(void* const* d_in, const int* in_sizes, int n_in,
                              void* d_out, int out_size) {
    const float* tokens = (const float*)d_in[0];
    const float* protos = (const float*)d_in[1];
    const int* fi;
    if (n_in >= 3) {
        fi = (const int*)d_in[2];
    } else {
        void* zp = nullptr;
        cudaGetSymbolAddress(&zp, g_zero);
        fi = (const int*)zp;
    }
    float* out = (float*)d_out;
    const int B = in_sizes[0] / (E_ * D_);

    cudaFuncSetAttribute(otng_hmma,
                         cudaFuncAttributeMaxDynamicSharedMemorySize, SMEM_BYTES);
    dim3 grid(E_, B / MTOK);
    otng_hmma<<<grid, THREADS, SMEM_BYTES>>>(tokens, protos, fi, out, B);
}

// round 7
// speedup vs baseline: 3.6404x; 1.8184x over previous
#include <cuda_runtime.h>
#include <cuda_bf16.h>
#include <cstdint>

#define E_ 8
#define D_ 512
#define P_ 32
#define MTOK 64             // tokens per CTA; M = 128 rows (64 token + 64 anchor)
#define THREADS 256
#define FULLM 0xffffffffu

// padded bf16 row for B tile: 512 + 8 = 520 elems = 1040 B (ldmatrix conflict-free)
#define ROWB 1040

// ---- smem layout (bytes) ----
#define SM_B     0                       // 32 * 1040 = 33280; reused as cross[128][34] after MMA
#define SM_S2    33280                   // 128 floats
#define SM_P2    33792                   // 32 floats
#define SMEM_BYTES 33920
#define SM_CROSS 0

__device__ int g_zero = 0;

static __device__ __forceinline__ uint32_t smem_u32(const void* p) {
    return (uint32_t)__cvta_generic_to_shared(p);
}

#define LDSM_X4(r0, r1, r2, r3, addr) \
    asm volatile("ldmatrix.sync.aligned.m8n8.x4.shared.b16 {%0,%1,%2,%3}, [%4];" \
        : "=r"(r0), "=r"(r1), "=r"(r2), "=r"(r3) : "r"(addr))

static __device__ __forceinline__ void mma16816(float* d, const uint32_t* a,
                                                uint32_t b0, uint32_t b1) {
    asm volatile(
        "mma.sync.aligned.m16n8k16.row.col.f32.bf16.bf16.f32 "
        "{%0,%1,%2,%3}, {%4,%5,%6,%7}, {%8,%9}, {%0,%1,%2,%3};"
        : "+f"(d[0]), "+f"(d[1]), "+f"(d[2]), "+f"(d[3])
        : "r"(a[0]), "r"(a[1]), "r"(a[2]), "r"(a[3]), "r"(b0), "r"(b1));
}

static __device__ __forceinline__ uint32_t packbf(float x, float y) {
    __nv_bfloat162 h = __floats2bfloat162_rn(x, y);
    return *reinterpret_cast<uint32_t*>(&h);
}

__global__ __launch_bounds__(THREADS, 4)
void otng_hmma(const float* __restrict__ tokens,
               const float* __restrict__ protos,
               const int* __restrict__ fi_ptr,
               float* __restrict__ out, int B) {
    extern __shared__ char smem[];
    const int e    = blockIdx.x;
    const int fi   = *fi_ptr;
    const int b0   = blockIdx.y * MTOK;
    const int tid  = threadIdx.x;
    const int wid  = tid >> 5;
    const int lane = tid & 31;
    const int BE   = B * E_;

    if (e == fi) {                        // trivial expert
        if (tid < MTOK) {
            int b = b0 + tid;
            out[b * E_ + e]      = 1.0f;
            out[BE + b * E_ + e] = 0.0f;
        }
        return;
    }

    const uint32_t sbase = smem_u32(smem);
    float* s2s = (float*)(smem + SM_S2);
    float* p2s = (float*)(smem + SM_P2);

    // ---- stage B: 32 prototypes of expert e, K-PERMUTED within each 16-k block ----
    // actual k = 4q..4q+3 goes to frag slots {2q, 2q+1} and {8+2q, 8+2q+1}.
    #pragma unroll 1
    for (int k = 0; k < 4; ++k) {
        const int p = wid + k * 8;                    // 0..31
        const float4* src = (const float4*)(protos + ((size_t)e * P_ + p) * D_);
        float nrm = 0.f;
        #pragma unroll
        for (int j = 0; j < 4; ++j) {
            float4 v = src[j * 32 + lane];            // actual k = j*128 + lane*4
            nrm = fmaf(v.x, v.x, fmaf(v.y, v.y, fmaf(v.z, v.z, fmaf(v.w, v.w, nrm))));
            const uint32_t blk = (uint32_t)(j * 8 + (lane >> 2));   // 16-k block idx
            const uint32_t q   = (uint32_t)(lane & 3);
            const uint32_t base = (uint32_t)(p * ROWB) + blk * 32u + q * 4u;
            *reinterpret_cast<uint32_t*>(smem + SM_B + base)      = packbf(v.x, v.y);
            *reinterpret_cast<uint32_t*>(smem + SM_B + base + 16) = packbf(v.z, v.w);
        }
        #pragma unroll
        for (int o = 16; o; o >>= 1) nrm += __shfl_xor_sync(FULLM, nrm, o);
        if (lane == 0) p2s[p] = nrm;
    }
    __syncthreads();

    // ---- HMMA GEMM, A fragments as single float4 per row per step (k-permuted) ----
    float acc[16];
    #pragma unroll
    for (int i = 0; i < 16; ++i) acc[i] = 0.f;
    float nrm0 = 0.f, nrm1 = 0.f;
    {
        const int gr  = lane >> 2;
        const int m   = lane & 3;
        const int r0  = wid * 16 + gr;                // r1 = r0 + 8, same region
        const int col = (r0 < 64) ? e : fi;
        const int bt0 = b0 + (r0 & 63);
        const float* pA0 = tokens + ((size_t)bt0 * E_ + col) * D_ + 4 * m;
        const float* pA1 = tokens + ((size_t)(bt0 + 8) * E_ + col) * D_ + 4 * m;

        const int bn  = (lane & 7) + ((lane >> 4) << 3);
        const int bk  = ((lane >> 3) & 1) * 8;
        const uint32_t bAddr0 = sbase + SM_B + (uint32_t)bn * ROWB + (uint32_t)(bk * 2);
        const uint32_t bAddr1 = bAddr0 + 16u * ROWB;

        #pragma unroll 4
        for (int s = 0; s < 32; ++s) {
            const int k0 = s * 16;
            float4 v0 = *(const float4*)(pA0 + k0);   // row r0,   actual k0+4m..+3
            float4 v1 = *(const float4*)(pA1 + k0);   // row r0+8, actual k0+4m..+3
            uint32_t a[4];
            a[0] = packbf(v0.x, v0.y); a[2] = packbf(v0.z, v0.w);
            a[1] = packbf(v1.x, v1.y); a[3] = packbf(v1.z, v1.w);
            nrm0 = fmaf(v0.x, v0.x, fmaf(v0.y, v0.y, fmaf(v0.z, v0.z, fmaf(v0.w, v0.w, nrm0))));
            nrm1 = fmaf(v1.x, v1.x, fmaf(v1.y, v1.y, fmaf(v1.z, v1.z, fmaf(v1.w, v1.w, nrm1))));

            uint32_t p0, p1, p2, p3, q0, q1, q2, q3;
            LDSM_X4(p0, p1, p2, p3, bAddr0 + s * 32);
            LDSM_X4(q0, q1, q2, q3, bAddr1 + s * 32);
            mma16816(acc + 0,  a, p0, p1);   // n 0-7
            mma16816(acc + 4,  a, p2, p3);   // n 8-15
            mma16816(acc + 8,  a, q0, q1);   // n 16-23
            mma16816(acc + 12, a, q2, q3);   // n 24-31
        }

        // row norms (fp32 pre-rounding): reduce across the quad (k pieces)
        nrm0 += __shfl_xor_sync(FULLM, nrm0, 1);
        nrm0 += __shfl_xor_sync(FULLM, nrm0, 2);
        nrm1 += __shfl_xor_sync(FULLM, nrm1, 1);
        nrm1 += __shfl_xor_sync(FULLM, nrm1, 2);
        if (m == 0) { s2s[r0] = nrm0; s2s[r0 + 8] = nrm1; }
    }
    __syncthreads();   // all ldsm reads of B done -> safe to overwrite with cross

    // ---- scatter accumulators to cross[128][34] (reuses B region) ----
    float* crossS = (float*)(smem + SM_CROSS);
    {
        const int r0 = wid * 16 + (lane >> 2);
        const int c0 = 2 * (lane & 3);
        #pragma unroll
        for (int nt = 0; nt < 4; ++nt) {
            const int col = nt * 8 + c0;
            *(float2*)(crossS + (size_t)r0 * 34 + col)       = make_float2(acc[nt*4+0], acc[nt*4+1]);
            *(float2*)(crossS + (size_t)(r0 + 8) * 34 + col) = make_float2(acc[nt*4+2], acc[nt*4+3]);
        }
    }
    __syncthreads();

    // ---- epilogue: Sinkhorn collapsed to scalar root-find  S(r)=sum_p 1/(1+c_p r)=16 ----
    const float p2v = p2s[lane];
    float cp[8], r[8], d01[8], c1v[8], Sa[8], Sb[8];
    #pragma unroll
    for (int t = 0; t < 8; ++t) {
        const int m = wid * 8 + t;
        float ct = crossS[(size_t)m * 34 + lane];
        float ca = crossS[(size_t)(64 + m) * 34 + lane];
        float c0 = fmaxf(fmaf(-2.f, ct, s2s[m])      + p2v, 0.f);
        float c1 = fmaxf(fmaf(-2.f, ca, s2s[64 + m]) + p2v, 0.f);
        d01[t] = c0 - c1;
        c1v[t] = c1;
        cp[t]  = __expf(20.f * (c0 - c1));            // kb/ka
        Sa[t]  = __expf(-20.f * c0);
        Sb[t]  = __expf(-20.f * c1);
    }
    #pragma unroll
    for (int o = 16; o; o >>= 1) {
        #pragma unroll
        for (int t = 0; t < 8; ++t) {
            Sa[t] += __shfl_xor_sync(FULLM, Sa[t], o);
            Sb[t] += __shfl_xor_sync(FULLM, Sb[t], o);
        }
    }
    #pragma unroll
    for (int t = 0; t < 8; ++t) r[t] = __fdividef(Sa[t], Sb[t]);   // reference iter 1

    #pragma unroll 1
    for (int it = 0; it < 6; ++it) {                  // Newton (monotone, convex)
        float f[8], g[8];
        #pragma unroll
        for (int t = 0; t < 8; ++t) {
            float u = __frcp_rn(fmaf(cp[t], r[t], 1.f));
            f[t] = u;
            g[t] = cp[t] * u * u;
        }
        #pragma unroll
        for (int o = 16; o; o >>= 1) {
            #pragma unroll
            for (int t = 0; t < 8; ++t) {
                f[t] += __shfl_xor_sync(FULLM, f[t], o);
                g[t] += __shfl_xor_sync(FULLM, g[t], o);
            }
        }
        #pragma unroll
        for (int t = 0; t < 8; ++t) {
            float rn = fmaf(f[t] - 16.f, __frcp_rn(g[t]), r[t]);
            r[t] = (rn > 0.f) ? rn : r[t] * 0.5f;
        }
    }

    float ot[8];
    #pragma unroll
    for (int t = 0; t < 8; ++t) {
        float w = __frcp_rn(fmaf(cp[t], r[t], 1.f));
        ot[t] = fmaf(w, d01[t], c1v[t]);               // w*c0 + (1-w)*c1
    }
    #pragma unroll
    for (int o = 16; o; o >>= 1) {
        #pragma unroll
        for (int t = 0; t < 8; ++t) ot[t] += __shfl_xor_sync(FULLM, ot[t], o);
    }
    if (lane == 0) {
        #pragma unroll
        for (int t = 0; t < 8; ++t) {
            const int b = b0 + wid * 8 + t;
            float o_  = ot[t] * (1.f / 32.f);
            float val = __fdividef(1.f, 1.f + __expf(6.f * (o_ - 0.25f)));
            out[b * E_ + e]      = val;
            out[BE + b * E_ + e] = o_;
        }
    }
}

// ---------------- launch ----------------
extern "C" void kernel_launch(void* const* d_in, const int* in_sizes, int n_in,
                              void* d_out, int out_size) {
    const float* tokens = (const float*)d_in[0];
    const float* protos = (const float*)d_in[1];
    const int* fi;
    if (n_in >= 3) {
        fi = (const int*)d_in[2];
    } else {
        void* zp = nullptr;
        cudaGetSymbolAddress(&zp, g_zero);
        fi = (const int*)zp;
    }
    float* out = (float*)d_out;
    const int B = in_sizes[0] / (E_ * D_);

    cudaFuncSetAttribute(otng_hmma,
                         cudaFuncAttributeMaxDynamicSharedMemorySize, SMEM_BYTES);
    dim3 grid(E_, B / MTOK);
    otng_hmma<<<grid, THREADS, SMEM_BYTES>>>(tokens, protos, fi, out, B);
}

// round 8
// speedup vs baseline: 4.3793x; 1.2030x over previous
#include <cuda_runtime.h>
#include <cuda_bf16.h>
#include <cstdint>

#define E_ 8
#define D_ 512
#define P_ 32
#define MTOK 64             // tokens per CTA; M = 128 rows (64 token + 64 anchor)
#define THREADS 256
#define FULLM 0xffffffffu

// padded bf16 row for B tile: 512 + 8 = 520 elems = 1040 B (ldmatrix conflict-free)
#define ROWB 1040

// ---- smem layout (bytes) ----
#define SM_B     0                       // 32 * 1040 = 33280; reused as cross[128][36] after MMA
#define SM_S2    33280                   // 128 floats
#define SM_P2    33792                   // 32 floats
#define SMEM_BYTES 33920
#define SM_CROSS 0
#define CSTRIDE  36                      // float4-aligned epilogue rows

__device__ int g_zero = 0;

static __device__ __forceinline__ uint32_t smem_u32(const void* p) {
    return (uint32_t)__cvta_generic_to_shared(p);
}

#define LDSM_X4(r0, r1, r2, r3, addr) \
    asm volatile("ldmatrix.sync.aligned.m8n8.x4.shared.b16 {%0,%1,%2,%3}, [%4];" \
        : "=r"(r0), "=r"(r1), "=r"(r2), "=r"(r3) : "r"(addr))

static __device__ __forceinline__ void mma16816(float* d, const uint32_t* a,
                                                uint32_t b0, uint32_t b1) {
    asm volatile(
        "mma.sync.aligned.m16n8k16.row.col.f32.bf16.bf16.f32 "
        "{%0,%1,%2,%3}, {%4,%5,%6,%7}, {%8,%9}, {%0,%1,%2,%3};"
        : "+f"(d[0]), "+f"(d[1]), "+f"(d[2]), "+f"(d[3])
        : "r"(a[0]), "r"(a[1]), "r"(a[2]), "r"(a[3]), "r"(b0), "r"(b1));
}

static __device__ __forceinline__ uint32_t packbf(float x, float y) {
    __nv_bfloat162 h = __floats2bfloat162_rn(x, y);
    return *reinterpret_cast<uint32_t*>(&h);
}

__global__ __launch_bounds__(THREADS, 4)
void otng_hmma(const float* __restrict__ tokens,
               const float* __restrict__ protos,
               const int* __restrict__ fi_ptr,
               float* __restrict__ out, int B) {
    extern __shared__ char smem[];
    const int e    = blockIdx.x;
    const int fi   = *fi_ptr;
    const int b0   = blockIdx.y * MTOK;
    const int tid  = threadIdx.x;
    const int wid  = tid >> 5;
    const int lane = tid & 31;
    const int BE   = B * E_;

    if (e == fi) {                        // trivial expert
        if (tid < MTOK) {
            int b = b0 + tid;
            out[b * E_ + e]      = 1.0f;
            out[BE + b * E_ + e] = 0.0f;
        }
        return;
    }

    const uint32_t sbase = smem_u32(smem);
    float* s2s = (float*)(smem + SM_S2);
    float* p2s = (float*)(smem + SM_P2);

    // ---- stage B: 32 prototypes of expert e, K-PERMUTED within each 16-k block ----
    // actual k = 4q..4q+3 goes to frag slots {2q, 2q+1} and {8+2q, 8+2q+1}.
    #pragma unroll 1
    for (int k = 0; k < 4; ++k) {
        const int p = wid + k * 8;                    // 0..31
        const float4* src = (const float4*)(protos + ((size_t)e * P_ + p) * D_);
        float nrm = 0.f;
        #pragma unroll
        for (int j = 0; j < 4; ++j) {
            float4 v = src[j * 32 + lane];            // actual k = j*128 + lane*4
            nrm = fmaf(v.x, v.x, fmaf(v.y, v.y, fmaf(v.z, v.z, fmaf(v.w, v.w, nrm))));
            const uint32_t blk = (uint32_t)(j * 8 + (lane >> 2));   // 16-k block idx
            const uint32_t q   = (uint32_t)(lane & 3);
            const uint32_t base = (uint32_t)(p * ROWB) + blk * 32u + q * 4u;
            *reinterpret_cast<uint32_t*>(smem + SM_B + base)      = packbf(v.x, v.y);
            *reinterpret_cast<uint32_t*>(smem + SM_B + base + 16) = packbf(v.z, v.w);
        }
        #pragma unroll
        for (int o = 16; o; o >>= 1) nrm += __shfl_xor_sync(FULLM, nrm, o);
        if (lane == 0) p2s[p] = nrm;
    }
    __syncthreads();

    // ---- HMMA GEMM, A fragments as single float4 per row per step (k-permuted) ----
    float acc[16];
    #pragma unroll
    for (int i = 0; i < 16; ++i) acc[i] = 0.f;
    float nrm0 = 0.f, nrm1 = 0.f;
    {
        const int gr  = lane >> 2;
        const int m   = lane & 3;
        const int r0  = wid * 16 + gr;                // r1 = r0 + 8, same region
        const int col = (r0 < 64) ? e : fi;
        const int bt0 = b0 + (r0 & 63);
        const float* pA0 = tokens + ((size_t)bt0 * E_ + col) * D_ + 4 * m;
        const float* pA1 = tokens + ((size_t)(bt0 + 8) * E_ + col) * D_ + 4 * m;

        const int bn  = (lane & 7) + ((lane >> 4) << 3);
        const int bk  = ((lane >> 3) & 1) * 8;
        const uint32_t bAddr0 = sbase + SM_B + (uint32_t)bn * ROWB + (uint32_t)(bk * 2);
        const uint32_t bAddr1 = bAddr0 + 16u * ROWB;

        #pragma unroll 4
        for (int s = 0; s < 32; ++s) {
            const int k0 = s * 16;
            float4 v0 = *(const float4*)(pA0 + k0);   // row r0,   actual k0+4m..+3
            float4 v1 = *(const float4*)(pA1 + k0);   // row r0+8, actual k0+4m..+3
            uint32_t a[4];
            a[0] = packbf(v0.x, v0.y); a[2] = packbf(v0.z, v0.w);
            a[1] = packbf(v1.x, v1.y); a[3] = packbf(v1.z, v1.w);
            nrm0 = fmaf(v0.x, v0.x, fmaf(v0.y, v0.y, fmaf(v0.z, v0.z, fmaf(v0.w, v0.w, nrm0))));
            nrm1 = fmaf(v1.x, v1.x, fmaf(v1.y, v1.y, fmaf(v1.z, v1.z, fmaf(v1.w, v1.w, nrm1))));

            uint32_t p0, p1, p2, p3, q0, q1, q2, q3;
            LDSM_X4(p0, p1, p2, p3, bAddr0 + s * 32);
            LDSM_X4(q0, q1, q2, q3, bAddr1 + s * 32);
            mma16816(acc + 0,  a, p0, p1);   // n 0-7
            mma16816(acc + 4,  a, p2, p3);   // n 8-15
            mma16816(acc + 8,  a, q0, q1);   // n 16-23
            mma16816(acc + 12, a, q2, q3);   // n 24-31
        }

        // row norms (fp32 pre-rounding): reduce across the quad (k pieces)
        nrm0 += __shfl_xor_sync(FULLM, nrm0, 1);
        nrm0 += __shfl_xor_sync(FULLM, nrm0, 2);
        nrm1 += __shfl_xor_sync(FULLM, nrm1, 1);
        nrm1 += __shfl_xor_sync(FULLM, nrm1, 2);
        if (m == 0) { s2s[r0] = nrm0; s2s[r0 + 8] = nrm1; }
    }
    __syncthreads();   // all ldsm reads of B done -> safe to overwrite with cross

    // ---- scatter accumulators to cross[128][36] (reuses B region) ----
    float* crossS = (float*)(smem + SM_CROSS);
    {
        const int r0 = wid * 16 + (lane >> 2);
        const int c0 = 2 * (lane & 3);
        #pragma unroll
        for (int nt = 0; nt < 4; ++nt) {
            const int col = nt * 8 + c0;
            *(float2*)(crossS + (size_t)r0 * CSTRIDE + col)       = make_float2(acc[nt*4+0], acc[nt*4+1]);
            *(float2*)(crossS + (size_t)(r0 + 8) * CSTRIDE + col) = make_float2(acc[nt*4+2], acc[nt*4+3]);
        }
    }
    __syncthreads();

    // ---- epilogue: quad = one token, lane holds 8 prototypes in registers ----
    // Sinkhorn fixed point: S(r) = sum_p 1/(1 + cp_p r) = 16; Newton from r=0 is
    // monotone-increasing & convergent (S convex decreasing, S(0)=32).
    {
        const int T  = tid >> 2;                      // token 0..63
        const int pl = (tid & 3) * 8;                 // this lane's 8 prototypes
        const float s2t = s2s[T];
        const float s2a = s2s[64 + T];

        float4 ct0 = *(const float4*)(crossS + (size_t)T * CSTRIDE + pl);
        float4 ct1 = *(const float4*)(crossS + (size_t)T * CSTRIDE + pl + 4);
        float4 ca0 = *(const float4*)(crossS + (size_t)(64 + T) * CSTRIDE + pl);
        float4 ca1 = *(const float4*)(crossS + (size_t)(64 + T) * CSTRIDE + pl + 4);
        float4 pv0 = *(const float4*)(p2s + pl);
        float4 pv1 = *(const float4*)(p2s + pl + 4);

        float ctv[8] = {ct0.x, ct0.y, ct0.z, ct0.w, ct1.x, ct1.y, ct1.z, ct1.w};
        float cav[8] = {ca0.x, ca0.y, ca0.z, ca0.w, ca1.x, ca1.y, ca1.z, ca1.w};
        float pvv[8] = {pv0.x, pv0.y, pv0.z, pv0.w, pv1.x, pv1.y, pv1.z, pv1.w};

        float cp[8], d01[8], sc1 = 0.f;
        #pragma unroll
        for (int j = 0; j < 8; ++j) {
            float c0 = fmaxf(fmaf(-2.f, ctv[j], s2t) + pvv[j], 0.f);
            float c1 = fmaxf(fmaf(-2.f, cav[j], s2a) + pvv[j], 0.f);
            d01[j] = c0 - c1;
            sc1   += c1;
            cp[j]  = __expf(20.f * (c0 - c1));        // kb/ka
        }

        float r = 0.f;
        #pragma unroll 1
        for (int it = 0; it < 8; ++it) {
            float f = 0.f, g = 0.f;
            #pragma unroll
            for (int j = 0; j < 8; ++j) {
                float u = __frcp_rn(fmaf(cp[j], r, 1.f));
                f += u;
                g = fmaf(cp[j], u * u, g);
            }
            f += __shfl_xor_sync(FULLM, f, 1);
            f += __shfl_xor_sync(FULLM, f, 2);
            g += __shfl_xor_sync(FULLM, g, 1);
            g += __shfl_xor_sync(FULLM, g, 2);
            r = fmaf(f - 16.f, __frcp_rn(g), r);
        }

        float ot = sc1;
        #pragma unroll
        for (int j = 0; j < 8; ++j) {
            float w = __frcp_rn(fmaf(cp[j], r, 1.f));
            ot = fmaf(w, d01[j], ot);                 // sum_p [w*d01 + c1]
        }
        ot += __shfl_xor_sync(FULLM, ot, 1);
        ot += __shfl_xor_sync(FULLM, ot, 2);

        if ((tid & 3) == 0) {
            const int b = b0 + T;
            float o_  = ot * (1.f / 32.f);
            float val = __fdividef(1.f, 1.f + __expf(6.f * (o_ - 0.25f)));
            out[b * E_ + e]      = val;
            out[BE + b * E_ + e] = o_;
        }
    }
}

// ---------------- launch ----------------
extern "C" void kernel_launch(void* const* d_in, const int* in_sizes, int n_in,
                              void* d_out, int out_size) {
    const float* tokens = (const float*)d_in[0];
    const float* protos = (const float*)d_in[1];
    const int* fi;
    if (n_in >= 3) {
        fi = (const int*)d_in[2];
    } else {
        void* zp = nullptr;
        cudaGetSymbolAddress(&zp, g_zero);
        fi = (const int*)zp;
    }
    float* out = (float*)d_out;
    const int B = in_sizes[0] / (E_ * D_);

    cudaFuncSetAttribute(otng_hmma,
                         cudaFuncAttributeMaxDynamicSharedMemorySize, SMEM_BYTES);
    dim3 grid(E_, B / MTOK);
    otng_hmma<<<grid, THREADS, SMEM_BYTES>>>(tokens, protos, fi, out, B);
}